// round 7
// baseline (speedup 1.0000x reference)
#include <cuda_runtime.h>
#include <cstdint>

#define VOCAB 50000
#define EMB   32
#define HID   64
#define H4    256
#define NCLS  3
#define BSZ   512
#define TLEN  512
#define FULL  0xffffffffu

// 51.2MB scratch: precomputed emb @ Wk + bias, per vocab entry (256 floats each)
__device__ float g_table[(size_t)VOCAB * H4];

// ---------- packed f32x2 helpers (sm_103a FFMA2 path, PTX-only) ----------
__device__ __forceinline__ unsigned long long pack2(float lo, float hi) {
    unsigned long long r;
    asm("mov.b64 %0, {%1, %2};" : "=l"(r) : "f"(lo), "f"(hi));
    return r;
}
__device__ __forceinline__ float2 unpack2(unsigned long long v) {
    float2 f;
    asm("mov.b64 {%0, %1}, %2;" : "=f"(f.x), "=f"(f.y) : "l"(v));
    return f;
}
#define FMA2(acc, a, b) \
    asm("fma.rn.f32x2 %0, %1, %2, %0;" : "+l"(acc) : "l"(a), "l"(b))
#define ADD2(d, a, b) \
    asm("add.rn.f32x2 %0, %1, %2;" : "=l"(d) : "l"(a), "l"(b))

__device__ __forceinline__ float ex2a(float x) {
    float r;
    asm("ex2.approx.ftz.f32 %0, %1;" : "=f"(r) : "f"(x));
    return r;
}
__device__ __forceinline__ float rcpa(float x) {
    float r;
    asm("rcp.approx.ftz.f32 %0, %1;" : "=f"(r) : "f"(x));
    return r;
}
#define LOG2E 1.4426950408889634f
__device__ __forceinline__ float sigf(float x) {
    return rcpa(1.0f + ex2a(-LOG2E * x));
}
__device__ __forceinline__ float tanhf_fast(float x) {
    return fmaf(2.0f, rcpa(1.0f + ex2a(-2.0f * LOG2E * x)), -1.0f);
}

// ---------- kernel 1: g_table[v][j] = sum_e emb[v][e]*Wk[e][j] + b[j] ----------
__global__ __launch_bounds__(256) void table_kernel(
    const float* __restrict__ emb, const float* __restrict__ Wk,
    const float* __restrict__ bias)
{
    __shared__ __align__(16) float sh_e[64 * EMB];
    const int j  = threadIdx.x;
    const int v0 = blockIdx.x * 64;

    unsigned long long wk2[16];
#pragma unroll
    for (int m = 0; m < 16; m++)
        wk2[m] = pack2(Wk[(2 * m) * H4 + j], Wk[(2 * m + 1) * H4 + j]);
    const float bj = bias[j];

    const int nrows = min(64, VOCAB - v0);
    const float4* src = reinterpret_cast<const float4*>(emb + (size_t)v0 * EMB);
    float4* dst = reinterpret_cast<float4*>(sh_e);
    for (int i = j; i < nrows * (EMB / 4); i += 256) dst[i] = src[i];
    __syncthreads();

    for (int r = 0; r < nrows; r++) {
        const ulonglong2* ev = reinterpret_cast<const ulonglong2*>(sh_e + r * EMB);
        unsigned long long a0 = 0ull, a1 = 0ull;
#pragma unroll
        for (int m = 0; m < 4; m++) {
            ulonglong2 p = ev[2 * m];
            ulonglong2 q = ev[2 * m + 1];
            FMA2(a0, p.x, wk2[4 * m + 0]);
            FMA2(a1, p.y, wk2[4 * m + 1]);
            FMA2(a0, q.x, wk2[4 * m + 2]);
            FMA2(a1, q.y, wk2[4 * m + 3]);
        }
        unsigned long long s;
        ADD2(s, a0, a1);
        float2 f = unpack2(s);
        g_table[(size_t)(v0 + r) * H4 + j] = bj + f.x + f.y;
    }
}

// ---------- kernel 2: recurrent LSTM, 2 batch rows per CTA, occ 2 ----------
// Quad-leader layout: warp w, lane l; unit u = 8w + (l>>2); gate = l&3;
// column jcol = gate*64 + u. After the dot, 6 shuffles deliver the 4 gate
// z's of unit u to lane g==0 (batch0) and g==2 (batch1). Gates in leaders,
// h published via predicated STS. Double-buffered h; ONE barrier per step.
__global__ __launch_bounds__(256, 2) void lstm_kernel(
    const int*   __restrict__ tokens,
    const float* __restrict__ Wr,
    const float* __restrict__ Wd,
    const float* __restrict__ bd,
    float*       __restrict__ out)
{
    __shared__ __align__(16) float sh_h[2][2][HID];  // [buf][batch][unit]
    __shared__ int sh_tok[2][TLEN + 1];
    __shared__ float sh_sink;

    const int j    = threadIdx.x;
    const int w    = j >> 5;
    const int l    = j & 31;
    const int u    = 8 * w + (l >> 2);     // unit 0..63
    const int g    = l & 3;                // gate slot within quad
    const int jcol = g * 64 + u;           // this thread's gate column
    const int base = l & ~3;
    const int b0   = blockIdx.x * 2;

    // shuffle source lanes (constant per thread, hoisted)
    const int sA0 = base + 1, sA1 = base + 2, sA2 = base + 3;  // for g==0 (z0)
    const int sB0 = base + 0, sB1 = base + 1, sB2 = base + 3;  // for g==2 (z1)
    const bool isB = (g == 2);

    // stage this CTA's 2 token rows (+1 pad so prefetch needs no clamp)
    for (int i = j; i < 2 * TLEN; i += 256) {
        int s = i >> 9, t = i & (TLEN - 1);
        sh_tok[s][t] = tokens[(size_t)(b0 + s) * TLEN + t];
    }
    if (j < 2) sh_tok[j][TLEN] = tokens[(size_t)(b0 + j) * TLEN + (TLEN - 1)];

    // Wr column jcol, packed over k
    unsigned long long wr2[32];
#pragma unroll
    for (int m = 0; m < 32; m++)
        wr2[m] = pack2(Wr[(2 * m) * H4 + jcol], Wr[(2 * m + 1) * H4 + jcol]);

    if (j < 2 * HID) sh_h[0][j >> 6][j & (HID - 1)] = 0.0f;
    float cst = 0.0f;  // cell state: (batch = g>>1, unit u) in leader lanes

    // anti-phase stagger: odd CTAs burn ~700 cyc (kept from R6 win)
    if (blockIdx.x & 1) {
        float d = (float)(sh_tok[0][0] & 1);
        const float z0c = 0.0f;
#pragma unroll 1
        for (int i = 0; i < 128; i++)
            asm("add.f32 %0, %0, %1;" : "+f"(d) : "f"(z0c));
        if (d > 2.0f) sh_sink = d;  // never true; keeps chain alive
    }
    __syncthreads();

    // prefetch xz for t=0 (table is L2-resident)
    float xzn0 = g_table[(size_t)sh_tok[0][0] * H4 + jcol];
    float xzn1 = g_table[(size_t)sh_tok[1][0] * H4 + jcol];

#pragma unroll 1
    for (int t = 0; t < TLEN; t++) {
        const float xz0 = xzn0, xz1 = xzn1;
        xzn0 = g_table[(size_t)sh_tok[0][t + 1] * H4 + jcol];
        xzn1 = g_table[(size_t)sh_tok[1][t + 1] * H4 + jcol];

        // z[s][jcol] = xz[s] + h[s] . Wr[:,jcol]
        const float* hb = sh_h[t & 1][0];
        const ulonglong2* h0 = reinterpret_cast<const ulonglong2*>(hb);
        const ulonglong2* h1 = reinterpret_cast<const ulonglong2*>(hb + HID);
        unsigned long long a0 = 0ull, a1 = 0ull, a2 = 0ull, a3 = 0ull;
        unsigned long long c0 = 0ull, c1 = 0ull, c2 = 0ull, c3 = 0ull;
#pragma unroll
        for (int m = 0; m < 8; m++) {
            ulonglong2 p0 = h0[2 * m];
            ulonglong2 q0 = h0[2 * m + 1];
            ulonglong2 p1 = h1[2 * m];
            ulonglong2 q1 = h1[2 * m + 1];
            const unsigned long long w0 = wr2[4 * m + 0];
            const unsigned long long w1 = wr2[4 * m + 1];
            const unsigned long long w2 = wr2[4 * m + 2];
            const unsigned long long w3 = wr2[4 * m + 3];
            FMA2(a0, p0.x, w0);
            FMA2(a1, p0.y, w1);
            FMA2(a2, q0.x, w2);
            FMA2(a3, q0.y, w3);
            FMA2(c0, p1.x, w0);
            FMA2(c1, p1.y, w1);
            FMA2(c2, q1.x, w2);
            FMA2(c3, q1.y, w3);
        }
        float z0, z1;
        {
            unsigned long long r0, r1;
            float2 f;
            ADD2(r0, a0, a1);
            ADD2(r1, a2, a3);
            ADD2(r0, r0, r1);
            f = unpack2(r0);
            z0 = xz0 + f.x + f.y;
            ADD2(r0, c0, c1);
            ADD2(r1, c2, c3);
            ADD2(r0, r0, r1);
            f = unpack2(r0);
            z1 = xz1 + f.x + f.y;
        }

        // quad exchange: 3 shuffles of z0 (batch0 -> g==0), 3 of z1 (-> g==2)
        const float A0 = __shfl_sync(FULL, z0, sA0);
        const float A1 = __shfl_sync(FULL, z0, sA1);
        const float A2 = __shfl_sync(FULL, z0, sA2);
        const float B0 = __shfl_sync(FULL, z1, sB0);
        const float B1 = __shfl_sync(FULL, z1, sB1);
        const float B2 = __shfl_sync(FULL, z1, sB2);

        // leader lanes: g==0 gates batch0 (own z0 = gate i), g==2 batch1
        const float zi = isB ? B0 : z0;
        const float zf = isB ? B1 : A0;
        const float zg = isB ? z1 : A1;
        const float zo = isB ? B2 : A2;

        const float ig = sigf(zi);
        const float fg = sigf(zf);
        const float og = sigf(zo);
        const float gg = tanhf_fast(zg);
        cst = fmaf(fg, cst, ig * gg);
        const float hv = og * tanhf_fast(cst);

        if ((g & 1) == 0) sh_h[(t & 1) ^ 1][g >> 1][u] = hv;
        __syncthreads();
    }

    // final h in buffer 0 (last write at t=511 targets (511&1)^1 = 0)
    if (j < 2) {
        const int s = j;
        float l0 = bd[0], l1 = bd[1], l2 = bd[2];
#pragma unroll 8
        for (int uu = 0; uu < HID; uu++) {
            const float h = sh_h[0][s][uu];
            l0 += h * Wd[uu * NCLS + 0];
            l1 += h * Wd[uu * NCLS + 1];
            l2 += h * Wd[uu * NCLS + 2];
        }
        const float m  = fmaxf(l0, fmaxf(l1, l2));
        const float e0 = ex2a(LOG2E * (l0 - m));
        const float e1 = ex2a(LOG2E * (l1 - m));
        const float e2 = ex2a(LOG2E * (l2 - m));
        const float inv = rcpa(e0 + e1 + e2);
        float* o = out + (size_t)(b0 + s) * NCLS;
        o[0] = e0 * inv;
        o[1] = e1 * inv;
        o[2] = e2 * inv;
    }
}

extern "C" void kernel_launch(void* const* d_in, const int* in_sizes, int n_in,
                              void* d_out, int out_size)
{
    const int*   tokens = (const int*)  d_in[0];
    const float* emb    = (const float*)d_in[1];
    const float* Wk     = (const float*)d_in[2];
    const float* Wr     = (const float*)d_in[3];
    const float* b      = (const float*)d_in[4];
    const float* Wd     = (const float*)d_in[5];
    const float* bd     = (const float*)d_in[6];
    float* out = (float*)d_out;

    table_kernel<<<(VOCAB + 63) / 64, 256>>>(emb, Wk, b);
    lstm_kernel<<<BSZ / 2, 256>>>(tokens, Wr, Wd, bd, out);
}

// round 8
// speedup vs baseline: 1.0222x; 1.0222x over previous
#include <cuda_runtime.h>
#include <cstdint>

#define VOCAB 50000
#define EMB   32
#define HID   64
#define H4    256
#define NCLS  3
#define BSZ   512
#define TLEN  512

// 51.2MB scratch: precomputed emb @ Wk + bias, per vocab entry (256 floats each)
__device__ float g_table[(size_t)VOCAB * H4];

// ---------- packed f32x2 helpers (sm_103a FFMA2 path, PTX-only) ----------
__device__ __forceinline__ unsigned long long pack2(float lo, float hi) {
    unsigned long long r;
    asm("mov.b64 %0, {%1, %2};" : "=l"(r) : "f"(lo), "f"(hi));
    return r;
}
__device__ __forceinline__ float2 unpack2(unsigned long long v) {
    float2 f;
    asm("mov.b64 {%0, %1}, %2;" : "=f"(f.x), "=f"(f.y) : "l"(v));
    return f;
}
#define FMA2(acc, a, b) \
    asm("fma.rn.f32x2 %0, %1, %2, %0;" : "+l"(acc) : "l"(a), "l"(b))
#define ADD2(d, a, b) \
    asm("add.rn.f32x2 %0, %1, %2;" : "=l"(d) : "l"(a), "l"(b))

__device__ __forceinline__ float ex2a(float x) {
    float r;
    asm("ex2.approx.ftz.f32 %0, %1;" : "=f"(r) : "f"(x));
    return r;
}
__device__ __forceinline__ float rcpa(float x) {
    float r;
    asm("rcp.approx.ftz.f32 %0, %1;" : "=f"(r) : "f"(x));
    return r;
}
#define LOG2E 1.4426950408889634f
__device__ __forceinline__ float sigf(float x) {
    return rcpa(1.0f + ex2a(-LOG2E * x));
}
__device__ __forceinline__ float tanhf_fast(float x) {
    return fmaf(2.0f, rcpa(1.0f + ex2a(-2.0f * LOG2E * x)), -1.0f);
}

// ---------- kernel 1: g_table[v][j] = sum_e emb[v][e]*Wk[e][j] + b[j] ----------
__global__ __launch_bounds__(256) void table_kernel(
    const float* __restrict__ emb, const float* __restrict__ Wk,
    const float* __restrict__ bias)
{
    __shared__ __align__(16) float sh_e[64 * EMB];
    const int j  = threadIdx.x;
    const int v0 = blockIdx.x * 64;

    unsigned long long wk2[16];
#pragma unroll
    for (int m = 0; m < 16; m++)
        wk2[m] = pack2(Wk[(2 * m) * H4 + j], Wk[(2 * m + 1) * H4 + j]);
    const float bj = bias[j];

    const int nrows = min(64, VOCAB - v0);
    const float4* src = reinterpret_cast<const float4*>(emb + (size_t)v0 * EMB);
    float4* dst = reinterpret_cast<float4*>(sh_e);
    for (int i = j; i < nrows * (EMB / 4); i += 256) dst[i] = src[i];
    __syncthreads();

    for (int r = 0; r < nrows; r++) {
        const ulonglong2* ev = reinterpret_cast<const ulonglong2*>(sh_e + r * EMB);
        unsigned long long a0 = 0ull, a1 = 0ull;
#pragma unroll
        for (int m = 0; m < 4; m++) {
            ulonglong2 p = ev[2 * m];
            ulonglong2 q = ev[2 * m + 1];
            FMA2(a0, p.x, wk2[4 * m + 0]);
            FMA2(a1, p.y, wk2[4 * m + 1]);
            FMA2(a0, q.x, wk2[4 * m + 2]);
            FMA2(a1, q.y, wk2[4 * m + 3]);
        }
        unsigned long long s;
        ADD2(s, a0, a1);
        float2 f = unpack2(s);
        g_table[(size_t)(v0 + r) * H4 + j] = bj + f.x + f.y;
    }
}

// ---------- kernel 2: recurrent LSTM, 2 batch rows per CTA, occ 2 ----------
// Two-batch software pipeline: per step,
//   z0-FMA ; publish hv1(t-1) ; bar1 ; gates0 (w0-1, latency hidden under
//   z1-FMA by all warps) ; publish hv0 ; bar2 ; gates1 (w2-3, hidden under
//   next step's z0-FMA).
// Gate MUFU chains are off the inter-barrier critical path.
__global__ __launch_bounds__(256, 2) void lstm_kernel(
    const int*   __restrict__ tokens,
    const float* __restrict__ Wr,
    const float* __restrict__ Wd,
    const float* __restrict__ bd,
    float*       __restrict__ out)
{
    __shared__ __align__(16) float sh_h0[2][HID];  // [buf][unit] batch0
    __shared__ __align__(16) float sh_h1[2][HID];  // [buf][unit] batch1
    __shared__ float sh_z0[H4];
    __shared__ float sh_z1[H4];
    __shared__ int   sh_tok[2][TLEN + 1];
    __shared__ float sh_sink;

    const int  j  = threadIdx.x;           // gate column 0..255
    const int  u  = j & (HID - 1);
    const bool g0 = (j < HID);             // gates batch0, unit u (warps 0-1)
    const bool g1 = (j >= HID) && (j < 2 * HID);  // gates batch1 (warps 2-3)
    const int  b0 = blockIdx.x * 2;

    // stage this CTA's 2 token rows (+1 pad so prefetch needs no clamp)
    for (int i = j; i < 2 * TLEN; i += 256) {
        int s = i >> 9, t = i & (TLEN - 1);
        sh_tok[s][t] = tokens[(size_t)(b0 + s) * TLEN + t];
    }
    if (j < 2) sh_tok[j][TLEN] = tokens[(size_t)(b0 + j) * TLEN + (TLEN - 1)];

    // Wr column j, packed over k: wr2[m] = (Wr[2m][j], Wr[2m+1][j])
    unsigned long long wr2[32];
#pragma unroll
    for (int m = 0; m < 32; m++)
        wr2[m] = pack2(Wr[(2 * m) * H4 + j], Wr[(2 * m + 1) * H4 + j]);

    if (g0) { sh_h0[0][u] = 0.0f; sh_h1[0][u] = 0.0f; }
    float cst = 0.0f;   // cell state: g0 -> (batch0,u), g1 -> (batch1,u)
    float hv1 = 0.0f;   // pending batch1 h (published at next loop top)

    // anti-phase stagger: odd CTAs burn ~700 cyc (kept from R6 win)
    if (blockIdx.x & 1) {
        float d = (float)(sh_tok[0][0] & 1);
        const float z0c = 0.0f;
#pragma unroll 1
        for (int i = 0; i < 128; i++)
            asm("add.f32 %0, %0, %1;" : "+f"(d) : "f"(z0c));
        if (d > 2.0f) sh_sink = d;  // never true; keeps chain alive
    }
    __syncthreads();

    // prefetch xz for t=0 (table is L2-resident)
    float xzn0 = g_table[(size_t)sh_tok[0][0] * H4 + j];
    float xzn1 = g_table[(size_t)sh_tok[1][0] * H4 + j];

#pragma unroll 1
    for (int t = 0; t < TLEN; t++) {
        const float xz0 = xzn0, xz1 = xzn1;
        xzn0 = g_table[(size_t)sh_tok[0][t + 1] * H4 + j];
        xzn1 = g_table[(size_t)sh_tok[1][t + 1] * H4 + j];

        // publish hv1 from previous step's gates1 into h1[t&1]
        // (t=0: writes 0.0 over the initialized 0.0 -- benign)
        if (g1) sh_h1[t & 1][u] = hv1;

        // ---- z0 = xz0 + h0[t&1] . Wr[:,j] ----
        {
            const ulonglong2* hv = reinterpret_cast<const ulonglong2*>(sh_h0[t & 1]);
            unsigned long long a0 = 0ull, a1 = 0ull, a2 = 0ull, a3 = 0ull;
#pragma unroll
            for (int m = 0; m < 8; m++) {
                ulonglong2 p = hv[2 * m];
                ulonglong2 q = hv[2 * m + 1];
                FMA2(a0, p.x, wr2[4 * m + 0]);
                FMA2(a1, p.y, wr2[4 * m + 1]);
                FMA2(a2, q.x, wr2[4 * m + 2]);
                FMA2(a3, q.y, wr2[4 * m + 3]);
            }
            unsigned long long r0, r1;
            ADD2(r0, a0, a1);
            ADD2(r1, a2, a3);
            ADD2(r0, r0, r1);
            float2 f = unpack2(r0);
            sh_z0[j] = xz0 + f.x + f.y;
        }
        __syncthreads();  // bar1: z0 complete, h1[t&1] published

        // ---- gates0 (warps 0-1): MUFU chain issues first, retires under z1 ----
        float hv0 = 0.0f;
        if (g0) {
            const float zi = sh_z0[u];
            const float zf = sh_z0[u + HID];
            const float zg = sh_z0[u + 2 * HID];
            const float zo = sh_z0[u + 3 * HID];
            const float ig = sigf(zi);
            const float fg = sigf(zf);
            const float og = sigf(zo);
            const float gg = tanhf_fast(zg);
            cst = fmaf(fg, cst, ig * gg);
            hv0 = og * tanhf_fast(cst);
        }

        // ---- z1 = xz1 + h1[t&1] . Wr[:,j] ----
        {
            const ulonglong2* hv = reinterpret_cast<const ulonglong2*>(sh_h1[t & 1]);
            unsigned long long a0 = 0ull, a1 = 0ull, a2 = 0ull, a3 = 0ull;
#pragma unroll
            for (int m = 0; m < 8; m++) {
                ulonglong2 p = hv[2 * m];
                ulonglong2 q = hv[2 * m + 1];
                FMA2(a0, p.x, wr2[4 * m + 0]);
                FMA2(a1, p.y, wr2[4 * m + 1]);
                FMA2(a2, q.x, wr2[4 * m + 2]);
                FMA2(a3, q.y, wr2[4 * m + 3]);
            }
            unsigned long long r0, r1;
            ADD2(r0, a0, a1);
            ADD2(r1, a2, a3);
            ADD2(r0, r0, r1);
            float2 f = unpack2(r0);
            sh_z1[j] = xz1 + f.x + f.y;
        }

        // publish hv0 into h0[(t&1)^1] (gate chain has retired by now)
        if (g0) sh_h0[(t & 1) ^ 1][u] = hv0;
        __syncthreads();  // bar2: z1 complete, h0[next] published

        // ---- gates1 (warps 2-3): hidden under next step's z0-FMA ----
        if (g1) {
            const float zi = sh_z1[u];
            const float zf = sh_z1[u + HID];
            const float zg = sh_z1[u + 2 * HID];
            const float zo = sh_z1[u + 3 * HID];
            const float ig = sigf(zi);
            const float fg = sigf(zf);
            const float og = sigf(zo);
            const float gg = tanhf_fast(zg);
            cst = fmaf(fg, cst, ig * gg);
            hv1 = og * tanhf_fast(cst);
        }
    }

    // publish final hv1 (t=511 -> buffer 0); h0 final already in buffer 0
    if (g1) sh_h1[0][u] = hv1;
    __syncthreads();

    // epilogue: dense(3) + softmax; thread 0 -> batch0, thread 1 -> batch1
    if (j < 2) {
        const float* hrow = (j == 0) ? sh_h0[0] : sh_h1[0];
        float l0 = bd[0], l1 = bd[1], l2 = bd[2];
#pragma unroll 8
        for (int uu = 0; uu < HID; uu++) {
            const float h = hrow[uu];
            l0 += h * Wd[uu * NCLS + 0];
            l1 += h * Wd[uu * NCLS + 1];
            l2 += h * Wd[uu * NCLS + 2];
        }
        const float m  = fmaxf(l0, fmaxf(l1, l2));
        const float e0 = ex2a(LOG2E * (l0 - m));
        const float e1 = ex2a(LOG2E * (l1 - m));
        const float e2 = ex2a(LOG2E * (l2 - m));
        const float inv = rcpa(e0 + e1 + e2);
        float* o = out + (size_t)(b0 + j) * NCLS;
        o[0] = e0 * inv;
        o[1] = e1 * inv;
        o[2] = e2 * inv;
    }
}

extern "C" void kernel_launch(void* const* d_in, const int* in_sizes, int n_in,
                              void* d_out, int out_size)
{
    const int*   tokens = (const int*)  d_in[0];
    const float* emb    = (const float*)d_in[1];
    const float* Wk     = (const float*)d_in[2];
    const float* Wr     = (const float*)d_in[3];
    const float* b      = (const float*)d_in[4];
    const float* Wd     = (const float*)d_in[5];
    const float* bd     = (const float*)d_in[6];
    float* out = (float*)d_out;

    table_kernel<<<(VOCAB + 63) / 64, 256>>>(emb, Wk, b);
    lstm_kernel<<<BSZ / 2, 256>>>(tokens, Wr, Wd, bd, out);
}

// round 9
// speedup vs baseline: 1.1364x; 1.1117x over previous
#include <cuda_runtime.h>
#include <cstdint>

#define VOCAB 50000
#define EMB   32
#define HID   64
#define H4    256
#define NCLS  3
#define BSZ   512
#define TLEN  512

// 51.2MB scratch: precomputed emb @ Wk + bias, per vocab entry (256 floats each)
__device__ float g_table[(size_t)VOCAB * H4];

// ---------- packed f32x2 helpers (sm_103a FFMA2 path, PTX-only) ----------
__device__ __forceinline__ unsigned long long pack2(float lo, float hi) {
    unsigned long long r;
    asm("mov.b64 %0, {%1, %2};" : "=l"(r) : "f"(lo), "f"(hi));
    return r;
}
__device__ __forceinline__ float2 unpack2(unsigned long long v) {
    float2 f;
    asm("mov.b64 {%0, %1}, %2;" : "=f"(f.x), "=f"(f.y) : "l"(v));
    return f;
}
#define FMA2(acc, a, b) \
    asm("fma.rn.f32x2 %0, %1, %2, %0;" : "+l"(acc) : "l"(a), "l"(b))
#define ADD2(d, a, b) \
    asm("add.rn.f32x2 %0, %1, %2;" : "=l"(d) : "l"(a), "l"(b))

__device__ __forceinline__ float ex2a(float x) {
    float r;
    asm("ex2.approx.ftz.f32 %0, %1;" : "=f"(r) : "f"(x));
    return r;
}
__device__ __forceinline__ float rcpa(float x) {
    float r;
    asm("rcp.approx.ftz.f32 %0, %1;" : "=f"(r) : "f"(x));
    return r;
}
#define LOG2E  1.4426950408889634f
#define LOG2E2 2.8853900817779268f

// ---------- kernel 1: g_table[v][j] = sum_e emb[v][e]*Wk[e][j] + b[j] ----------
// 2 columns per thread, STG.64 stores. Block stages 64 vocab rows; threads
// 0-127 handle rows 0-31, threads 128-255 rows 32-63, each thread 2 cols.
__global__ __launch_bounds__(256) void table_kernel(
    const float* __restrict__ emb, const float* __restrict__ Wk,
    const float* __restrict__ bias)
{
    __shared__ __align__(16) float sh_e[64 * EMB];
    const int tid = threadIdx.x;
    const int c0  = (tid & 127) * 2;        // first of 2 columns
    const int rg  = tid >> 7;               // row group 0/1
    const int v0  = blockIdx.x * 64;

    // wk packed over e for both columns: wkA for col c0, wkB for col c0+1
    unsigned long long wkA[16], wkB[16];
#pragma unroll
    for (int m = 0; m < 16; m++) {
        wkA[m] = pack2(Wk[(2 * m) * H4 + c0],     Wk[(2 * m + 1) * H4 + c0]);
        wkB[m] = pack2(Wk[(2 * m) * H4 + c0 + 1], Wk[(2 * m + 1) * H4 + c0 + 1]);
    }
    const float bA = bias[c0], bB = bias[c0 + 1];

    const int nrows = min(64, VOCAB - v0);
    const float4* src = reinterpret_cast<const float4*>(emb + (size_t)v0 * EMB);
    float4* dst = reinterpret_cast<float4*>(sh_e);
    for (int i = tid; i < nrows * (EMB / 4); i += 256) dst[i] = src[i];
    __syncthreads();

    const int r_lo = rg * 32;
    const int r_hi = min(r_lo + 32, nrows);
    for (int r = r_lo; r < r_hi; r++) {
        const ulonglong2* ev = reinterpret_cast<const ulonglong2*>(sh_e + r * EMB);
        unsigned long long a0 = 0ull, a1 = 0ull, b0 = 0ull, b1 = 0ull;
#pragma unroll
        for (int m = 0; m < 8; m++) {
            ulonglong2 p = ev[m];
            FMA2(a0, p.x, wkA[2 * m]);
            FMA2(a1, p.y, wkA[2 * m + 1]);
            FMA2(b0, p.x, wkB[2 * m]);
            FMA2(b1, p.y, wkB[2 * m + 1]);
        }
        unsigned long long sa, sb;
        ADD2(sa, a0, a1);
        ADD2(sb, b0, b1);
        float2 fa = unpack2(sa), fb = unpack2(sb);
        float2 o;
        o.x = bA + fa.x + fa.y;
        o.y = bB + fb.x + fb.y;
        *reinterpret_cast<float2*>(&g_table[(size_t)(v0 + r) * H4 + c0]) = o;
    }
}

// ---------- kernel 2: recurrent LSTM, 2 batch rows per CTA, occ 2 ----------
// R6 topology (best known): thread j owns gate-column j for both batches
// (64 FMA2/step); gates in threads 0-127 (1 gate-warp per SMSP -> MUFU-
// minimal); h double-buffered; 2 barriers/step; odd-CTA anti-phase stagger.
// R9 deltas: fused-rcp gates (10->8 MUFU), xz folded into acc init, padded
// token prefetch (no clamp SELs).
__global__ __launch_bounds__(256, 2) void lstm_kernel(
    const int*   __restrict__ tokens,
    const float* __restrict__ Wr,
    const float* __restrict__ Wd,
    const float* __restrict__ bd,
    float*       __restrict__ out)
{
    __shared__ __align__(16) float sh_h[2][2][HID];  // [buf][batch][unit]
    __shared__ float sh_z[2][H4];
    __shared__ int   sh_tok[2][TLEN + 1];
    __shared__ float sh_sink;

    const int j    = threadIdx.x;     // gate column 0..255
    const int su_s = j >> 6;          // gate-phase batch (j<128)
    const int su_u = j & (HID - 1);   // gate-phase unit
    const int b0   = blockIdx.x * 2;

    // stage this CTA's 2 token rows (+1 pad so prefetch needs no clamp)
    for (int i = j; i < 2 * TLEN; i += 256) {
        int s = i >> 9, t = i & (TLEN - 1);
        sh_tok[s][t] = tokens[(size_t)(b0 + s) * TLEN + t];
    }
    if (j < 2) sh_tok[j][TLEN] = tokens[(size_t)(b0 + j) * TLEN + (TLEN - 1)];

    // Wr column j, packed over k: wr2[m] = (Wr[2m][j], Wr[2m+1][j])
    unsigned long long wr2[32];
#pragma unroll
    for (int m = 0; m < 32; m++)
        wr2[m] = pack2(Wr[(2 * m) * H4 + j], Wr[(2 * m + 1) * H4 + j]);

    if (j < 2 * HID) sh_h[0][su_s][su_u] = 0.0f;
    float cst = 0.0f;  // cell state for (su_s, su_u); valid for j<128

    // anti-phase stagger: odd CTAs burn ~700 cyc (R6 win, kept)
    if (blockIdx.x & 1) {
        float d = (float)(sh_tok[0][0] & 1);
        const float z0c = 0.0f;
#pragma unroll 1
        for (int i = 0; i < 128; i++)
            asm("add.f32 %0, %0, %1;" : "+f"(d) : "f"(z0c));
        if (d > 2.0f) sh_sink = d;  // never true; keeps chain alive
    }
    __syncthreads();

    // prefetch xz for t=0 (table is L2-resident)
    float xzn0 = g_table[(size_t)sh_tok[0][0] * H4 + j];
    float xzn1 = g_table[(size_t)sh_tok[1][0] * H4 + j];

#pragma unroll 1
    for (int t = 0; t < TLEN; t++) {
        const float xz0 = xzn0, xz1 = xzn1;
        xzn0 = g_table[(size_t)sh_tok[0][t + 1] * H4 + j];
        xzn1 = g_table[(size_t)sh_tok[1][t + 1] * H4 + j];

        // z[s][j] = xz[s] + h[s] . Wr[:,j]  (xz folded into acc init)
        const float* hb = sh_h[t & 1][0];
        const ulonglong2* h0 = reinterpret_cast<const ulonglong2*>(hb);
        const ulonglong2* h1 = reinterpret_cast<const ulonglong2*>(hb + HID);
        unsigned long long a0 = pack2(xz0, 0.0f), a1 = 0ull, a2 = 0ull, a3 = 0ull;
        unsigned long long c0 = pack2(xz1, 0.0f), c1 = 0ull, c2 = 0ull, c3 = 0ull;
#pragma unroll
        for (int m = 0; m < 8; m++) {
            ulonglong2 p0 = h0[2 * m];
            ulonglong2 q0 = h0[2 * m + 1];
            ulonglong2 p1 = h1[2 * m];
            ulonglong2 q1 = h1[2 * m + 1];
            const unsigned long long w0 = wr2[4 * m + 0];
            const unsigned long long w1 = wr2[4 * m + 1];
            const unsigned long long w2 = wr2[4 * m + 2];
            const unsigned long long w3 = wr2[4 * m + 3];
            FMA2(a0, p0.x, w0);
            FMA2(a1, p0.y, w1);
            FMA2(a2, q0.x, w2);
            FMA2(a3, q0.y, w3);
            FMA2(c0, p1.x, w0);
            FMA2(c1, p1.y, w1);
            FMA2(c2, q1.x, w2);
            FMA2(c3, q1.y, w3);
        }
        {
            unsigned long long r0, r1;
            float2 f;
            ADD2(r0, a0, a1);
            ADD2(r1, a2, a3);
            ADD2(r0, r0, r1);
            f = unpack2(r0);
            sh_z[0][j] = f.x + f.y;
            ADD2(r0, c0, c1);
            ADD2(r1, c2, c3);
            ADD2(r0, r0, r1);
            f = unpack2(r0);
            sh_z[1][j] = f.x + f.y;
        }
        __syncthreads();

        // gate phase: threads 0..127, fused-rcp form (5 EX2 + 3 RCP)
        if (j < 2 * HID) {
            const float zi = sh_z[su_s][su_u];
            const float zf = sh_z[su_s][su_u + HID];
            const float zg = sh_z[su_s][su_u + 2 * HID];
            const float zo = sh_z[su_s][su_u + 3 * HID];
            const float ei = ex2a(-LOG2E * zi);
            const float ef = ex2a(-LOG2E * zf);
            const float eg = ex2a(-LOG2E2 * zg);
            const float eo = ex2a(-LOG2E * zo);
            const float fg = rcpa(1.0f + ef);
            // i*tanh(g) = (1-eg) * rcp((1+ei)*(1+eg))
            const float r1 = rcpa((1.0f + ei) * (1.0f + eg));
            cst = fmaf(fg, cst, (1.0f - eg) * r1);
            // o*tanh(c) = (1-ec) * rcp((1+eo)*(1+ec))
            const float ec = ex2a(-LOG2E2 * cst);
            const float r2 = rcpa((1.0f + eo) * (1.0f + ec));
            sh_h[(t & 1) ^ 1][su_s][su_u] = (1.0f - ec) * r2;
        }
        __syncthreads();
    }

    // final h in buffer 0 (last write at t=511 targets (511&1)^1 = 0)
    if (j < 2) {
        const int s = j;
        float l0 = bd[0], l1 = bd[1], l2 = bd[2];
#pragma unroll 8
        for (int uu = 0; uu < HID; uu++) {
            const float h = sh_h[0][s][uu];
            l0 += h * Wd[uu * NCLS + 0];
            l1 += h * Wd[uu * NCLS + 1];
            l2 += h * Wd[uu * NCLS + 2];
        }
        const float m  = fmaxf(l0, fmaxf(l1, l2));
        const float e0 = ex2a(LOG2E * (l0 - m));
        const float e1 = ex2a(LOG2E * (l1 - m));
        const float e2 = ex2a(LOG2E * (l2 - m));
        const float inv = rcpa(e0 + e1 + e2);
        float* o = out + (size_t)(b0 + s) * NCLS;
        o[0] = e0 * inv;
        o[1] = e1 * inv;
        o[2] = e2 * inv;
    }
}

extern "C" void kernel_launch(void* const* d_in, const int* in_sizes, int n_in,
                              void* d_out, int out_size)
{
    const int*   tokens = (const int*)  d_in[0];
    const float* emb    = (const float*)d_in[1];
    const float* Wk     = (const float*)d_in[2];
    const float* Wr     = (const float*)d_in[3];
    const float* b      = (const float*)d_in[4];
    const float* Wd     = (const float*)d_in[5];
    const float* bd     = (const float*)d_in[6];
    float* out = (float*)d_out;

    table_kernel<<<(VOCAB + 63) / 64, 256>>>(emb, Wk, b);
    lstm_kernel<<<BSZ / 2, 256>>>(tokens, Wr, Wd, bd, out);
}

// round 10
// speedup vs baseline: 1.2144x; 1.0686x over previous
#include <cuda_runtime.h>
#include <cstdint>

#define VOCAB 50000
#define EMB   32
#define HID   64
#define H4    256
#define NCLS  3
#define BSZ   512
#define TLEN  512

// 51.2MB scratch: precomputed emb @ Wk + bias, per vocab entry (256 floats each)
__device__ float g_table[(size_t)VOCAB * H4];

// ---------- packed f32x2 helpers (sm_103a FFMA2 path, PTX-only) ----------
__device__ __forceinline__ unsigned long long pack2(float lo, float hi) {
    unsigned long long r;
    asm("mov.b64 %0, {%1, %2};" : "=l"(r) : "f"(lo), "f"(hi));
    return r;
}
__device__ __forceinline__ float2 unpack2(unsigned long long v) {
    float2 f;
    asm("mov.b64 {%0, %1}, %2;" : "=f"(f.x), "=f"(f.y) : "l"(v));
    return f;
}
#define FMA2(acc, a, b) \
    asm("fma.rn.f32x2 %0, %1, %2, %0;" : "+l"(acc) : "l"(a), "l"(b))
#define ADD2(d, a, b) \
    asm("add.rn.f32x2 %0, %1, %2;" : "=l"(d) : "l"(a), "l"(b))

__device__ __forceinline__ float ex2a(float x) {
    float r;
    asm("ex2.approx.ftz.f32 %0, %1;" : "=f"(r) : "f"(x));
    return r;
}
__device__ __forceinline__ float rcpa(float x) {
    float r;
    asm("rcp.approx.ftz.f32 %0, %1;" : "=f"(r) : "f"(x));
    return r;
}
#define LOG2E  1.4426950408889634f
#define LOG2E2 2.8853900817779268f

// ---------- kernel 1: g_table[v][j] = sum_e emb[v][e]*Wk[e][j] + b[j] ----------
// 2 columns per thread, STG.64 stores (R9, kept).
__global__ __launch_bounds__(256) void table_kernel(
    const float* __restrict__ emb, const float* __restrict__ Wk,
    const float* __restrict__ bias)
{
    __shared__ __align__(16) float sh_e[64 * EMB];
    const int tid = threadIdx.x;
    const int c0  = (tid & 127) * 2;
    const int rg  = tid >> 7;
    const int v0  = blockIdx.x * 64;

    unsigned long long wkA[16], wkB[16];
#pragma unroll
    for (int m = 0; m < 16; m++) {
        wkA[m] = pack2(Wk[(2 * m) * H4 + c0],     Wk[(2 * m + 1) * H4 + c0]);
        wkB[m] = pack2(Wk[(2 * m) * H4 + c0 + 1], Wk[(2 * m + 1) * H4 + c0 + 1]);
    }
    const float bA = bias[c0], bB = bias[c0 + 1];

    const int nrows = min(64, VOCAB - v0);
    const float4* src = reinterpret_cast<const float4*>(emb + (size_t)v0 * EMB);
    float4* dst = reinterpret_cast<float4*>(sh_e);
    for (int i = tid; i < nrows * (EMB / 4); i += 256) dst[i] = src[i];
    __syncthreads();

    const int r_lo = rg * 32;
    const int r_hi = min(r_lo + 32, nrows);
    for (int r = r_lo; r < r_hi; r++) {
        const ulonglong2* ev = reinterpret_cast<const ulonglong2*>(sh_e + r * EMB);
        unsigned long long a0 = 0ull, a1 = 0ull, b0 = 0ull, b1 = 0ull;
#pragma unroll
        for (int m = 0; m < 8; m++) {
            ulonglong2 p = ev[m];
            FMA2(a0, p.x, wkA[2 * m]);
            FMA2(a1, p.y, wkA[2 * m + 1]);
            FMA2(b0, p.x, wkB[2 * m]);
            FMA2(b1, p.y, wkB[2 * m + 1]);
        }
        unsigned long long sa, sb;
        ADD2(sa, a0, a1);
        ADD2(sb, b0, b1);
        float2 fa = unpack2(sa), fb = unpack2(sb);
        float2 o;
        o.x = bA + fa.x + fa.y;
        o.y = bB + fb.x + fb.y;
        *reinterpret_cast<float2*>(&g_table[(size_t)(v0 + r) * H4 + c0]) = o;
    }
}

// ---------- kernel 2: recurrent LSTM, 2 batch rows per CTA, occ 2 ----------
// 128 threads/CTA (4 warps). Thread j owns gate columns j AND j+128 for both
// batches (128 FMA2/step); each 16B h chunk is loaded ONCE and feeds both
// columns' accumulators -> LDS wavefronts per SM halved vs R6. Gate phase:
// ALL 128 threads, (s=j>>6, u=j&63). Double-buffered h; 2 barriers/step;
// odd-CTA anti-phase stagger; fused-rcp gates.
__global__ __launch_bounds__(128, 2) void lstm_kernel(
    const int*   __restrict__ tokens,
    const float* __restrict__ Wr,
    const float* __restrict__ Wd,
    const float* __restrict__ bd,
    float*       __restrict__ out)
{
    __shared__ __align__(16) float sh_h[2][2][HID];  // [buf][batch][unit]
    __shared__ float sh_z[2][H4];
    __shared__ int   sh_tok[2][TLEN + 1];
    __shared__ float sh_sink;

    const int j    = threadIdx.x;     // 0..127: owns cols j and j+128
    const int jB   = j + 128;
    const int su_s = j >> 6;          // gate-phase batch
    const int su_u = j & (HID - 1);   // gate-phase unit
    const int b0   = blockIdx.x * 2;

    // stage this CTA's 2 token rows (+1 pad so prefetch needs no clamp)
    for (int i = j; i < 2 * TLEN; i += 128) {
        int s = i >> 9, t = i & (TLEN - 1);
        sh_tok[s][t] = tokens[(size_t)(b0 + s) * TLEN + t];
    }
    if (j < 2) sh_tok[j][TLEN] = tokens[(size_t)(b0 + j) * TLEN + (TLEN - 1)];

    // Wr columns j and jB, packed over k (64 b64 regs total)
    unsigned long long wA[32], wB[32];
#pragma unroll
    for (int m = 0; m < 32; m++) {
        wA[m] = pack2(Wr[(2 * m) * H4 + j],  Wr[(2 * m + 1) * H4 + j]);
        wB[m] = pack2(Wr[(2 * m) * H4 + jB], Wr[(2 * m + 1) * H4 + jB]);
    }

    sh_h[0][su_s][su_u] = 0.0f;   // 128 threads cover [2][64] exactly
    float cst = 0.0f;             // cell state for (su_s, su_u)

    // anti-phase stagger: odd CTAs burn ~700 cyc (R6 win, kept)
    if (blockIdx.x & 1) {
        float d = (float)(sh_tok[0][0] & 1);
        const float z0c = 0.0f;
#pragma unroll 1
        for (int i = 0; i < 128; i++)
            asm("add.f32 %0, %0, %1;" : "+f"(d) : "f"(z0c));
        if (d > 2.0f) sh_sink = d;  // never true; keeps chain alive
    }
    __syncthreads();

    // prefetch xz for t=0 (table is L2-resident): 2 cols x 2 batches
    float xzA0 = g_table[(size_t)sh_tok[0][0] * H4 + j];
    float xzB0 = g_table[(size_t)sh_tok[0][0] * H4 + jB];
    float xzA1 = g_table[(size_t)sh_tok[1][0] * H4 + j];
    float xzB1 = g_table[(size_t)sh_tok[1][0] * H4 + jB];

#pragma unroll 1
    for (int t = 0; t < TLEN; t++) {
        const float cA0 = xzA0, cB0 = xzB0, cA1 = xzA1, cB1 = xzB1;
        const int tk0 = sh_tok[0][t + 1], tk1 = sh_tok[1][t + 1];
        xzA0 = g_table[(size_t)tk0 * H4 + j];
        xzB0 = g_table[(size_t)tk0 * H4 + jB];
        xzA1 = g_table[(size_t)tk1 * H4 + j];
        xzB1 = g_table[(size_t)tk1 * H4 + jB];

        const float* hb = sh_h[t & 1][0];
        const ulonglong2* h0 = reinterpret_cast<const ulonglong2*>(hb);
        const ulonglong2* h1 = reinterpret_cast<const ulonglong2*>(hb + HID);

        // ---- batch 0: cols j and jB share the h chunks ----
        {
            unsigned long long a0 = pack2(cA0, 0.0f), a1 = 0ull, a2 = 0ull, a3 = 0ull;
            unsigned long long d0 = pack2(cB0, 0.0f), d1 = 0ull, d2 = 0ull, d3 = 0ull;
#pragma unroll
            for (int m = 0; m < 8; m++) {
                ulonglong2 p = h0[2 * m];
                ulonglong2 q = h0[2 * m + 1];
                FMA2(a0, p.x, wA[4 * m + 0]);
                FMA2(a1, p.y, wA[4 * m + 1]);
                FMA2(a2, q.x, wA[4 * m + 2]);
                FMA2(a3, q.y, wA[4 * m + 3]);
                FMA2(d0, p.x, wB[4 * m + 0]);
                FMA2(d1, p.y, wB[4 * m + 1]);
                FMA2(d2, q.x, wB[4 * m + 2]);
                FMA2(d3, q.y, wB[4 * m + 3]);
            }
            unsigned long long r0, r1;
            float2 f;
            ADD2(r0, a0, a1);
            ADD2(r1, a2, a3);
            ADD2(r0, r0, r1);
            f = unpack2(r0);
            sh_z[0][j] = f.x + f.y;
            ADD2(r0, d0, d1);
            ADD2(r1, d2, d3);
            ADD2(r0, r0, r1);
            f = unpack2(r0);
            sh_z[0][jB] = f.x + f.y;
        }
        // ---- batch 1 ----
        {
            unsigned long long a0 = pack2(cA1, 0.0f), a1 = 0ull, a2 = 0ull, a3 = 0ull;
            unsigned long long d0 = pack2(cB1, 0.0f), d1 = 0ull, d2 = 0ull, d3 = 0ull;
#pragma unroll
            for (int m = 0; m < 8; m++) {
                ulonglong2 p = h1[2 * m];
                ulonglong2 q = h1[2 * m + 1];
                FMA2(a0, p.x, wA[4 * m + 0]);
                FMA2(a1, p.y, wA[4 * m + 1]);
                FMA2(a2, q.x, wA[4 * m + 2]);
                FMA2(a3, q.y, wA[4 * m + 3]);
                FMA2(d0, p.x, wB[4 * m + 0]);
                FMA2(d1, p.y, wB[4 * m + 1]);
                FMA2(d2, q.x, wB[4 * m + 2]);
                FMA2(d3, q.y, wB[4 * m + 3]);
            }
            unsigned long long r0, r1;
            float2 f;
            ADD2(r0, a0, a1);
            ADD2(r1, a2, a3);
            ADD2(r0, r0, r1);
            f = unpack2(r0);
            sh_z[1][j] = f.x + f.y;
            ADD2(r0, d0, d1);
            ADD2(r1, d2, d3);
            ADD2(r0, r0, r1);
            f = unpack2(r0);
            sh_z[1][jB] = f.x + f.y;
        }
        __syncthreads();

        // gate phase: ALL 128 threads, fused-rcp form (5 EX2 + 3 RCP)
        {
            const float zi = sh_z[su_s][su_u];
            const float zf = sh_z[su_s][su_u + HID];
            const float zg = sh_z[su_s][su_u + 2 * HID];
            const float zo = sh_z[su_s][su_u + 3 * HID];
            const float ei = ex2a(-LOG2E * zi);
            const float ef = ex2a(-LOG2E * zf);
            const float eg = ex2a(-LOG2E2 * zg);
            const float eo = ex2a(-LOG2E * zo);
            const float fg = rcpa(1.0f + ef);
            const float r1 = rcpa((1.0f + ei) * (1.0f + eg));
            cst = fmaf(fg, cst, (1.0f - eg) * r1);
            const float ec = ex2a(-LOG2E2 * cst);
            const float r2 = rcpa((1.0f + eo) * (1.0f + ec));
            sh_h[(t & 1) ^ 1][su_s][su_u] = (1.0f - ec) * r2;
        }
        __syncthreads();
    }

    // final h in buffer 0 (last write at t=511 targets (511&1)^1 = 0)
    if (j < 2) {
        const int s = j;
        float l0 = bd[0], l1 = bd[1], l2 = bd[2];
#pragma unroll 8
        for (int uu = 0; uu < HID; uu++) {
            const float h = sh_h[0][s][uu];
            l0 += h * Wd[uu * NCLS + 0];
            l1 += h * Wd[uu * NCLS + 1];
            l2 += h * Wd[uu * NCLS + 2];
        }
        const float m  = fmaxf(l0, fmaxf(l1, l2));
        const float e0 = ex2a(LOG2E * (l0 - m));
        const float e1 = ex2a(LOG2E * (l1 - m));
        const float e2 = ex2a(LOG2E * (l2 - m));
        const float inv = rcpa(e0 + e1 + e2);
        float* o = out + (size_t)(b0 + s) * NCLS;
        o[0] = e0 * inv;
        o[1] = e1 * inv;
        o[2] = e2 * inv;
    }
}

extern "C" void kernel_launch(void* const* d_in, const int* in_sizes, int n_in,
                              void* d_out, int out_size)
{
    const int*   tokens = (const int*)  d_in[0];
    const float* emb    = (const float*)d_in[1];
    const float* Wk     = (const float*)d_in[2];
    const float* Wr     = (const float*)d_in[3];
    const float* b      = (const float*)d_in[4];
    const float* Wd     = (const float*)d_in[5];
    const float* bd     = (const float*)d_in[6];
    float* out = (float*)d_out;

    table_kernel<<<(VOCAB + 63) / 64, 256>>>(emb, Wk, b);
    lstm_kernel<<<BSZ / 2, 128>>>(tokens, Wr, Wd, bd, out);
}